// round 3
// baseline (speedup 1.0000x reference)
#include <cuda_runtime.h>
#include <math.h>

#define BB 32
#define SS 2048
#define HH 768
#define EE 2
#define MTOT (BB*SS)
#define LN_EPS 1e-5f

// Scratch (no allocations allowed)
__device__ float g_pooled[BB*HH];
__device__ float g_probs[BB*EE];
__device__ int   g_idx[BB];

// ---------------------------------------------------------------------------
// Kernel 1: mean over sequence dim. inputs [B, S, H] -> g_pooled [B, H]
// ---------------------------------------------------------------------------
__global__ void pool_kernel(const float* __restrict__ in) {
    int idx = blockIdx.x * blockDim.x + threadIdx.x;
    if (idx >= BB * HH) return;
    int b = idx / HH;
    int h = idx - b * HH;
    const float* p = in + (size_t)b * SS * HH + h;
    float s0 = 0.f, s1 = 0.f, s2 = 0.f, s3 = 0.f;
    #pragma unroll 4
    for (int i = 0; i < SS; i += 4) {
        s0 += p[(size_t)(i + 0) * HH];
        s1 += p[(size_t)(i + 1) * HH];
        s2 += p[(size_t)(i + 2) * HH];
        s3 += p[(size_t)(i + 3) * HH];
    }
    g_pooled[idx] = (s0 + s1 + s2 + s3) * (1.0f / SS);
}

// ---------------------------------------------------------------------------
// Kernel 2: LayerNorm -> router linear -> softmax -> argmax, per batch row.
// One block (256 threads) per batch.
// ---------------------------------------------------------------------------
__global__ void router_kernel(const float* __restrict__ gamma,
                              const float* __restrict__ beta,
                              const float* __restrict__ rw,
                              const float* __restrict__ rb) {
    int b = blockIdx.x;
    int t = threadIdx.x;  // 256 threads, 3 h-values each (768 = 3*256)
    __shared__ float red[256];

    float x0 = g_pooled[b * HH + t];
    float x1 = g_pooled[b * HH + t + 256];
    float x2 = g_pooled[b * HH + t + 512];

    // mean
    red[t] = x0 + x1 + x2;
    __syncthreads();
    for (int o = 128; o > 0; o >>= 1) { if (t < o) red[t] += red[t + o]; __syncthreads(); }
    float mu = red[0] * (1.0f / HH);
    __syncthreads();

    // variance (population)
    float d0 = x0 - mu, d1 = x1 - mu, d2 = x2 - mu;
    red[t] = d0 * d0 + d1 * d1 + d2 * d2;
    __syncthreads();
    for (int o = 128; o > 0; o >>= 1) { if (t < o) red[t] += red[t + o]; __syncthreads(); }
    float rstd = rsqrtf(red[0] * (1.0f / HH) + LN_EPS);
    __syncthreads();

    // normalize + router matvec (E=2)
    float n0 = d0 * rstd * gamma[t]       + beta[t];
    float n1 = d1 * rstd * gamma[t + 256] + beta[t + 256];
    float n2 = d2 * rstd * gamma[t + 512] + beta[t + 512];
    float l0 = n0 * rw[t * EE]           + n1 * rw[(t + 256) * EE]     + n2 * rw[(t + 512) * EE];
    float l1 = n0 * rw[t * EE + 1]       + n1 * rw[(t + 256) * EE + 1] + n2 * rw[(t + 512) * EE + 1];

    red[t] = l0;
    __syncthreads();
    for (int o = 128; o > 0; o >>= 1) { if (t < o) red[t] += red[t + o]; __syncthreads(); }
    l0 = red[0];
    __syncthreads();
    red[t] = l1;
    __syncthreads();
    for (int o = 128; o > 0; o >>= 1) { if (t < o) red[t] += red[t + o]; __syncthreads(); }

    if (t == 0) {
        l1 = red[0];
        l0 += rb[0];
        l1 += rb[1];
        float m  = fmaxf(l0, l1);
        float e0 = expf(l0 - m);
        float e1 = expf(l1 - m);
        float inv = 1.0f / (e0 + e1);
        g_probs[b * 2 + 0] = e0 * inv;
        g_probs[b * 2 + 1] = e1 * inv;
        g_idx[b] = (l1 > l0) ? 1 : 0;  // argmax, ties -> 0 (matches jnp.argmax)
    }
}

// ---------------------------------------------------------------------------
// Kernel 3: aux (load-balance) loss -> out[B*S*H]
// ---------------------------------------------------------------------------
__global__ void aux_kernel(float* __restrict__ out) {
    float a0 = 0.f, a1 = 0.f;
    for (int b = 0; b < BB; b++) { a0 += g_probs[2 * b]; a1 += g_probs[2 * b + 1]; }
    a0 *= (1.0f / BB);
    a1 *= (1.0f / BB);
    float d0 = a0 - 0.5f, d1 = a1 - 0.5f;
    out[0] = 0.01f * 0.5f * (d0 * d0 + d1 * d1);
}

// ---------------------------------------------------------------------------
// GELU (tanh approximation, matches jax.nn.gelu approximate=True)
// ---------------------------------------------------------------------------
__device__ __forceinline__ float gelu_f(float x) {
    float u = 0.7978845608028654f * x * (1.0f + 0.044715f * x * x);
    float a = __expf(2.0f * fabsf(u));            // saturates safely to +inf
    float t = copysignf(1.0f - 2.0f / (a + 1.0f), u);
    return 0.5f * x * (1.0f + t);
}

// ---------------------------------------------------------------------------
// Kernel 4: expert GEMM + bias + GELU.
// C[m, n] = gelu( sum_k A[m,k] * W_e[k,n] + bias_e[n] ),  e = g_idx[m / S]
// 128x128x16 tiles, 256 threads, 8x8 per-thread microtile, fp32.
// ---------------------------------------------------------------------------
__global__ __launch_bounds__(256, 2) void gemm_gelu_kernel(
    const float* __restrict__ A,     // [MTOT, H]
    const float* __restrict__ W,     // [E, H, H]
    const float* __restrict__ bias,  // [E, H]
    float* __restrict__ C)           // [MTOT, H]
{
    const int BM = 128, BN = 128, BK = 16;
    __shared__ float As[BK][BM + 4];   // transposed A tile (132-float stride keeps 16B align)
    __shared__ float Bs[BK][BN + 4];

    int tid = threadIdx.x;
    int tx = tid & 15;          // N direction (0..15)
    int ty = tid >> 4;          // M direction (0..15)
    int m0 = blockIdx.y * BM;
    int n0 = blockIdx.x * BN;

    int bat = m0 >> 11;         // 2048 rows per batch; 128 | 2048 so tile is single-expert
    int e = g_idx[bat];
    const float* Wp = W + (size_t)e * HH * HH;
    const float* bp = bias + e * HH;
    const float* Ap = A + (size_t)m0 * HH;

    // global-load assignments
    int aRow  = tid >> 2;       // 0..63  (two rows: aRow, aRow+64)
    int aCol4 = tid & 3;        // 0..3   (float4 within 16-float K slab)
    int bRow  = tid >> 5;       // 0..7   (two rows: bRow, bRow+8)
    int bCol4 = tid & 31;       // 0..31  (float4 within 128-float N tile)

    float acc[8][8];
    #pragma unroll
    for (int i = 0; i < 8; i++)
        #pragma unroll
        for (int j = 0; j < 8; j++) acc[i][j] = 0.f;

    for (int kt = 0; kt < HH; kt += BK) {
        float4 a0 = *(const float4*)(Ap + (size_t)aRow        * HH + kt + aCol4 * 4);
        float4 a1 = *(const float4*)(Ap + (size_t)(aRow + 64) * HH + kt + aCol4 * 4);
        float4 b0 = *(const float4*)(Wp + (size_t)(kt + bRow)     * HH + n0 + bCol4 * 4);
        float4 b1 = *(const float4*)(Wp + (size_t)(kt + bRow + 8) * HH + n0 + bCol4 * 4);

        __syncthreads();  // previous iteration's consumers done

        As[aCol4 * 4 + 0][aRow] = a0.x;
        As[aCol4 * 4 + 1][aRow] = a0.y;
        As[aCol4 * 4 + 2][aRow] = a0.z;
        As[aCol4 * 4 + 3][aRow] = a0.w;
        As[aCol4 * 4 + 0][aRow + 64] = a1.x;
        As[aCol4 * 4 + 1][aRow + 64] = a1.y;
        As[aCol4 * 4 + 2][aRow + 64] = a1.z;
        As[aCol4 * 4 + 3][aRow + 64] = a1.w;
        *(float4*)&Bs[bRow][bCol4 * 4]     = b0;
        *(float4*)&Bs[bRow + 8][bCol4 * 4] = b1;

        __syncthreads();

        #pragma unroll
        for (int k = 0; k < BK; k++) {
            float ar[8], br[8];
            *(float4*)(ar)     = *(const float4*)&As[k][ty * 8];
            *(float4*)(ar + 4) = *(const float4*)&As[k][ty * 8 + 4];
            *(float4*)(br)     = *(const float4*)&Bs[k][tx * 8];
            *(float4*)(br + 4) = *(const float4*)&Bs[k][tx * 8 + 4];
            #pragma unroll
            for (int i = 0; i < 8; i++)
                #pragma unroll
                for (int j = 0; j < 8; j++)
                    acc[i][j] = fmaf(ar[i], br[j], acc[i][j]);
        }
    }

    // epilogue: bias + gelu + store
    float bv[8];
    #pragma unroll
    for (int j = 0; j < 8; j++) bv[j] = bp[n0 + tx * 8 + j];

    #pragma unroll
    for (int i = 0; i < 8; i++) {
        int m = m0 + ty * 8 + i;
        float o[8];
        #pragma unroll
        for (int j = 0; j < 8; j++) o[j] = gelu_f(acc[i][j] + bv[j]);
        *(float4*)&C[(size_t)m * HH + n0 + tx * 8]     = *(float4*)(o);
        *(float4*)&C[(size_t)m * HH + n0 + tx * 8 + 4] = *(float4*)(o + 4);
    }
}

// ---------------------------------------------------------------------------
// Launch
// ---------------------------------------------------------------------------
extern "C" void kernel_launch(void* const* d_in, const int* in_sizes, int n_in,
                              void* d_out, int out_size) {
    const float* inputs   = (const float*)d_in[0];  // [B, S, H]
    const float* ln_gamma = (const float*)d_in[1];  // [H]
    const float* ln_beta  = (const float*)d_in[2];  // [H]
    const float* router_w = (const float*)d_in[3];  // [H, E]
    const float* router_b = (const float*)d_in[4];  // [E]
    const float* expert_w = (const float*)d_in[5];  // [E, H, H]
    const float* expert_b = (const float*)d_in[6];  // [E, H]
    float* out = (float*)d_out;

    pool_kernel<<<(BB * HH + 255) / 256, 256>>>(inputs);
    router_kernel<<<BB, 256>>>(ln_gamma, ln_beta, router_w, router_b);

    dim3 grid(HH / 128, MTOT / 128);  // (6, 512)
    gemm_gelu_kernel<<<grid, 256>>>(inputs, expert_w, expert_b, out);

    if (out_size > BB * SS * HH) {
        aux_kernel<<<1, 1>>>(out + (size_t)BB * SS * HH);
    }
}

// round 5
// speedup vs baseline: 2.0711x; 2.0711x over previous
#include <cuda_runtime.h>
#include <cuda_bf16.h>
#include <math.h>
#include <stdint.h>

#define BB 32
#define SS 2048
#define HH 768
#define EE 2
#define MTOT (BB*SS)
#define LN_EPS 1e-5f

// GEMM tiling: CTA 128x256, 8 warps of 64x64, BK=32 (bf16), 2-stage cp.async
#define BK 32
#define NCHUNK (HH/BK)           // 24
#define ROWB 80                  // padded row: 32 bf16 = 64B + 16B pad
#define A_TILE 10240             // 128*80
#define B_TILE 20480             // 256*80
#define OFF_AH 0
#define OFF_AL 10240
#define OFF_BH 20480
#define OFF_BL 40960
#define STAGE 61440
#define SMEM_TOTAL (2*STAGE)     // 122880

// -------- scratch (no allocations allowed) --------
__device__ float g_part[BB*32*HH];
__device__ float g_pooled[BB*HH];
__device__ float g_probs[BB*EE];
__device__ int   g_idx[BB];
__device__ __nv_bfloat16 g_ah[(size_t)MTOT*HH];   // A hi
__device__ __nv_bfloat16 g_al[(size_t)MTOT*HH];   // A lo
__device__ __nv_bfloat16 g_wt_hi[EE*HH*HH];        // W^T hi [e][n][k]
__device__ __nv_bfloat16 g_wt_lo[EE*HH*HH];        // W^T lo

// ---------------------------------------------------------------------------
// helpers
// ---------------------------------------------------------------------------
__device__ __forceinline__ uint32_t smem_u32(const void* p) {
    return (uint32_t)__cvta_generic_to_shared(p);
}
__device__ __forceinline__ void cp16(uint32_t dst, const void* src) {
    asm volatile("cp.async.cg.shared.global [%0], [%1], 16;" :: "r"(dst), "l"(src));
}
#define CP_COMMIT() asm volatile("cp.async.commit_group;" ::: "memory")
#define CP_WAIT0()  asm volatile("cp.async.wait_group 0;" ::: "memory")
#define CP_WAIT1()  asm volatile("cp.async.wait_group 1;" ::: "memory")

__device__ __forceinline__ void ldsm4(uint32_t* r, uint32_t addr) {
    asm volatile("ldmatrix.sync.aligned.m8n8.x4.shared.b16 {%0,%1,%2,%3}, [%4];"
                 : "=r"(r[0]), "=r"(r[1]), "=r"(r[2]), "=r"(r[3]) : "r"(addr));
}
__device__ __forceinline__ void mma16816(float* c, const uint32_t* a, const uint32_t* b) {
    asm volatile(
        "mma.sync.aligned.m16n8k16.row.col.f32.bf16.bf16.f32 "
        "{%0,%1,%2,%3}, {%4,%5,%6,%7}, {%8,%9}, {%0,%1,%2,%3};"
        : "+f"(c[0]), "+f"(c[1]), "+f"(c[2]), "+f"(c[3])
        : "r"(a[0]), "r"(a[1]), "r"(a[2]), "r"(a[3]), "r"(b[0]), "r"(b[1]));
}
__device__ __forceinline__ uint32_t pack2(__nv_bfloat16 a, __nv_bfloat16 b) {
    return (uint32_t)__bfloat16_as_ushort(a) | ((uint32_t)__bfloat16_as_ushort(b) << 16);
}

// FMA/ALU-only GELU (tanh approx == sigmoid form): no MUFU in the hot epilogue.
__device__ __forceinline__ float gelu_f(float x) {
    float u = 0.7978845608028654f * x * (1.0f + 0.044715f * x * x);
    float z = 2.885390081777927f * u;                 // 2u*log2(e)
    z = fminf(fmaxf(z, -30.0f), 30.0f);
    float nf = rintf(z);
    float f = z - nf;
    float p = 1.5403530e-4f;                          // 2^f Taylor deg 6
    p = fmaf(p, f, 1.3333558e-3f);
    p = fmaf(p, f, 9.6181291e-3f);
    p = fmaf(p, f, 5.5504109e-2f);
    p = fmaf(p, f, 2.4022651e-1f);
    p = fmaf(p, f, 6.9314718e-1f);
    p = fmaf(p, f, 1.0f);
    float sc = __int_as_float(((int)nf + 127) << 23);
    float e = p * sc;                                 // e^{2u}
    float D = e + 1.0f;
    float r = __int_as_float(0x7EF311C3u - __float_as_int(D));
    r = r * (2.0f - D * r);
    r = r * (2.0f - D * r);
    r = r * (2.0f - D * r);                           // r = 1/(1+e^{2u})
    return x * (1.0f - r);
}

// ---------------------------------------------------------------------------
// Fused pool partials + A bf16 hi/lo split. grid BB*32, block 192.
// ---------------------------------------------------------------------------
__global__ void pool_split_kernel(const float* __restrict__ in) {
    int blk = blockIdx.x;
    int b = blk >> 5, c = blk & 31;
    int t = threadIdx.x;                  // col4 = 4t .. 4t+3
    size_t row0 = (size_t)b * SS + (size_t)c * 64;
    float4 s = {0.f, 0.f, 0.f, 0.f};
    for (int i = 0; i < 64; i++) {
        size_t m = row0 + i;
        float4 v = *(const float4*)(in + m * HH + 4 * t);
        s.x += v.x; s.y += v.y; s.z += v.z; s.w += v.w;
        __nv_bfloat16 h0 = __float2bfloat16_rn(v.x);
        __nv_bfloat16 h1 = __float2bfloat16_rn(v.y);
        __nv_bfloat16 h2 = __float2bfloat16_rn(v.z);
        __nv_bfloat16 h3 = __float2bfloat16_rn(v.w);
        uint2 hp, lp;
        hp.x = pack2(h0, h1); hp.y = pack2(h2, h3);
        lp.x = pack2(__float2bfloat16_rn(v.x - __bfloat162float(h0)),
                     __float2bfloat16_rn(v.y - __bfloat162float(h1)));
        lp.y = pack2(__float2bfloat16_rn(v.z - __bfloat162float(h2)),
                     __float2bfloat16_rn(v.w - __bfloat162float(h3)));
        *(uint2*)(g_ah + m * HH + 4 * t) = hp;
        *(uint2*)(g_al + m * HH + 4 * t) = lp;
    }
    *(float4*)(g_part + (size_t)blk * HH + 4 * t) = s;
}

__global__ void pool2_kernel() {
    int idx = blockIdx.x * blockDim.x + threadIdx.x;
    if (idx >= BB * HH) return;
    int b = idx / HH, h = idx - b * HH;
    float s = 0.f;
    #pragma unroll
    for (int c = 0; c < 32; c++) s += g_part[(size_t)(b * 32 + c) * HH + h];
    g_pooled[idx] = s * (1.0f / SS);
}

// ---------------------------------------------------------------------------
// W[e][k][n] -> W^T hi/lo [e][n][k], tiled transpose. grid (24,24,2), blk (32,8)
// ---------------------------------------------------------------------------
__global__ void convert_w_kernel(const float* __restrict__ W) {
    __shared__ float tile[32][33];
    int e = blockIdx.z;
    int k0 = blockIdx.y * 32, n0 = blockIdx.x * 32;
    int tx = threadIdx.x, ty = threadIdx.y;
    const float* Wp = W + (size_t)e * HH * HH;
    for (int i = ty; i < 32; i += 8)
        tile[i][tx] = Wp[(size_t)(k0 + i) * HH + n0 + tx];
    __syncthreads();
    __nv_bfloat16* oh = g_wt_hi + (size_t)e * HH * HH;
    __nv_bfloat16* ol = g_wt_lo + (size_t)e * HH * HH;
    for (int i = ty; i < 32; i += 8) {
        float w = tile[tx][i];
        __nv_bfloat16 hi = __float2bfloat16_rn(w);
        oh[(size_t)(n0 + i) * HH + k0 + tx] = hi;
        ol[(size_t)(n0 + i) * HH + k0 + tx] =
            __float2bfloat16_rn(w - __bfloat162float(hi));
    }
}

// ---------------------------------------------------------------------------
// Router: LN -> linear -> softmax -> argmax. One block per batch.
// ---------------------------------------------------------------------------
__global__ void router_kernel(const float* __restrict__ gamma,
                              const float* __restrict__ beta,
                              const float* __restrict__ rw,
                              const float* __restrict__ rb) {
    int b = blockIdx.x;
    int t = threadIdx.x;
    __shared__ float red[256];

    float x0 = g_pooled[b * HH + t];
    float x1 = g_pooled[b * HH + t + 256];
    float x2 = g_pooled[b * HH + t + 512];

    red[t] = x0 + x1 + x2;
    __syncthreads();
    for (int o = 128; o > 0; o >>= 1) { if (t < o) red[t] += red[t + o]; __syncthreads(); }
    float mu = red[0] * (1.0f / HH);
    __syncthreads();

    float d0 = x0 - mu, d1 = x1 - mu, d2 = x2 - mu;
    red[t] = d0 * d0 + d1 * d1 + d2 * d2;
    __syncthreads();
    for (int o = 128; o > 0; o >>= 1) { if (t < o) red[t] += red[t + o]; __syncthreads(); }
    float rstd = rsqrtf(red[0] * (1.0f / HH) + LN_EPS);
    __syncthreads();

    float n0 = d0 * rstd * gamma[t]       + beta[t];
    float n1 = d1 * rstd * gamma[t + 256] + beta[t + 256];
    float n2 = d2 * rstd * gamma[t + 512] + beta[t + 512];
    float l0 = n0 * rw[t * EE]     + n1 * rw[(t + 256) * EE]     + n2 * rw[(t + 512) * EE];
    float l1 = n0 * rw[t * EE + 1] + n1 * rw[(t + 256) * EE + 1] + n2 * rw[(t + 512) * EE + 1];

    red[t] = l0;
    __syncthreads();
    for (int o = 128; o > 0; o >>= 1) { if (t < o) red[t] += red[t + o]; __syncthreads(); }
    l0 = red[0];
    __syncthreads();
    red[t] = l1;
    __syncthreads();
    for (int o = 128; o > 0; o >>= 1) { if (t < o) red[t] += red[t + o]; __syncthreads(); }

    if (t == 0) {
        l1 = red[0];
        l0 += rb[0];
        l1 += rb[1];
        float m  = fmaxf(l0, l1);
        float e0 = expf(l0 - m);
        float e1 = expf(l1 - m);
        float inv = 1.0f / (e0 + e1);
        g_probs[b * 2 + 0] = e0 * inv;
        g_probs[b * 2 + 1] = e1 * inv;
        g_idx[b] = (l1 > l0) ? 1 : 0;
    }
}

__global__ void aux_kernel(float* __restrict__ out) {
    float a0 = 0.f, a1 = 0.f;
    for (int b = 0; b < BB; b++) { a0 += g_probs[2 * b]; a1 += g_probs[2 * b + 1]; }
    a0 *= (1.0f / BB);
    a1 *= (1.0f / BB);
    float d0 = a0 - 0.5f, d1 = a1 - 0.5f;
    out[0] = 0.01f * 0.5f * (d0 * d0 + d1 * d1);
}

// ---------------------------------------------------------------------------
// GEMM stage loader: 12 x cp.async(16B) per thread (A hi/lo 128 rows, B hi/lo 256)
// ---------------------------------------------------------------------------
__device__ __forceinline__ void load_stage(
    uint32_t sb, int buf, int m0, int n0, int kt,
    const __nv_bfloat16* __restrict__ WH,
    const __nv_bfloat16* __restrict__ WL, int tid)
{
    uint32_t st = sb + (uint32_t)buf * STAGE;
    #pragma unroll
    for (int j = 0; j < 12; j++) {
        int gid = j * 256 + tid;
        if (gid < 1024) {
            int a = gid >> 9; int rem = gid & 511;
            int r = rem >> 2, kc = rem & 3;
            const __nv_bfloat16* base = a ? g_al : g_ah;
            cp16(st + (uint32_t)a * A_TILE + r * ROWB + kc * 16,
                 base + (size_t)(m0 + r) * HH + kt + kc * 8);
        } else {
            int g2 = gid - 1024;
            int bs = g2 >> 10; int rem = g2 & 1023;
            int r = rem >> 2, kc = rem & 3;
            const __nv_bfloat16* base = bs ? WL : WH;
            cp16(st + OFF_BH + (uint32_t)bs * B_TILE + r * ROWB + kc * 16,
                 base + (size_t)(n0 + r) * HH + kt + kc * 8);
        }
    }
    CP_COMMIT();
}

// ---------------------------------------------------------------------------
// GEMM: C = gelu(A @ W_e + b_e), mma.sync bf16 3-term split
// ---------------------------------------------------------------------------
__global__ __launch_bounds__(256, 1) void gemm_tc_kernel(
    const float* __restrict__ bias,
    float* __restrict__ C)
{
    extern __shared__ char sm[];
    uint32_t sb = smem_u32(sm);
    int tid = threadIdx.x, lane = tid & 31, wid = tid >> 5;
    int mw = wid & 1;          // 0..1  -> m offset *64
    int nw = wid >> 1;         // 0..3  -> n offset *64
    int n0 = blockIdx.x * 256;
    int m0 = blockIdx.y * 128;

    int e = g_idx[m0 >> 11];
    const __nv_bfloat16* WH = g_wt_hi + (size_t)e * HH * HH;
    const __nv_bfloat16* WL = g_wt_lo + (size_t)e * HH * HH;

    float acc[4][8][4];
    #pragma unroll
    for (int mt = 0; mt < 4; mt++)
        #pragma unroll
        for (int nt = 0; nt < 8; nt++)
            #pragma unroll
            for (int q = 0; q < 4; q++) acc[mt][nt][q] = 0.f;

    // per-thread ldmatrix base offsets (within a stage)
    uint32_t aoff = (uint32_t)((mw * 64 + (lane & 15)) * ROWB + (lane >> 4) * 16);
    uint32_t boff = OFF_BH +
        (uint32_t)((nw * 64 + (lane & 7) + ((lane & 16) >> 1)) * ROWB + ((lane >> 3) & 1) * 16);

    load_stage(sb, 0, m0, n0, 0, WH, WL, tid);

    for (int i = 0; i < NCHUNK; i++) {
        if (i < NCHUNK - 1) {
            load_stage(sb, (i + 1) & 1, m0, n0, (i + 1) * BK, WH, WL, tid);
            CP_WAIT1();
        } else {
            CP_WAIT0();
        }
        __syncthreads();

        uint32_t st = sb + (uint32_t)(i & 1) * STAGE;
        #pragma unroll
        for (int ks = 0; ks < 2; ks++) {
            #pragma unroll
            for (int p = 0; p < 3; p++) {   // (Ah,Bh),(Ah,Bl),(Al,Bh)
                uint32_t ab = st + aoff + (p == 2 ? (uint32_t)OFF_AL : 0u) + ks * 32;
                uint32_t bb = st + boff + (p == 1 ? (uint32_t)B_TILE : 0u) + ks * 32;
                uint32_t a[4][4], b[4][4];
                #pragma unroll
                for (int mt = 0; mt < 4; mt++) ldsm4(a[mt], ab + mt * (16 * ROWB));
                #pragma unroll
                for (int nt2 = 0; nt2 < 4; nt2++) ldsm4(b[nt2], bb + nt2 * (16 * ROWB));
                #pragma unroll
                for (int mt = 0; mt < 4; mt++)
                    #pragma unroll
                    for (int nt = 0; nt < 8; nt++)
                        mma16816(acc[mt][nt], a[mt], &b[nt >> 1][(nt & 1) * 2]);
            }
        }
        __syncthreads();
    }

    // epilogue: bias + gelu + store (float2 per half-tile)
    int ncol = n0 + nw * 64;
    const float* bp = bias + e * HH + ncol + 2 * (lane & 3);
    float2 bv[8];
    #pragma unroll
    for (int nt = 0; nt < 8; nt++) bv[nt] = *(const float2*)(bp + nt * 8);

    #pragma unroll
    for (int mt = 0; mt < 4; mt++) {
        int r0 = m0 + mw * 64 + mt * 16 + (lane >> 2);
        float* crow0 = C + (size_t)r0 * HH + ncol + 2 * (lane & 3);
        float* crow1 = crow0 + (size_t)8 * HH;
        #pragma unroll
        for (int nt = 0; nt < 8; nt++) {
            float2 o0, o1;
            o0.x = gelu_f(acc[mt][nt][0] + bv[nt].x);
            o0.y = gelu_f(acc[mt][nt][1] + bv[nt].y);
            o1.x = gelu_f(acc[mt][nt][2] + bv[nt].x);
            o1.y = gelu_f(acc[mt][nt][3] + bv[nt].y);
            *(float2*)(crow0 + nt * 8) = o0;
            *(float2*)(crow1 + nt * 8) = o1;
        }
    }
}

// ---------------------------------------------------------------------------
// Launch (gemm is 6th launch so ncu -s 5 -c 1 profiles it)
// ---------------------------------------------------------------------------
extern "C" void kernel_launch(void* const* d_in, const int* in_sizes, int n_in,
                              void* d_out, int out_size) {
    const float* inputs   = (const float*)d_in[0];
    const float* ln_gamma = (const float*)d_in[1];
    const float* ln_beta  = (const float*)d_in[2];
    const float* router_w = (const float*)d_in[3];
    const float* router_b = (const float*)d_in[4];
    const float* expert_w = (const float*)d_in[5];
    const float* expert_b = (const float*)d_in[6];
    float* out = (float*)d_out;

    cudaFuncSetAttribute(gemm_tc_kernel,
                         cudaFuncAttributeMaxDynamicSharedMemorySize, SMEM_TOTAL);

    pool_split_kernel<<<BB * 32, 192>>>(inputs);                       // 1
    pool2_kernel<<<(BB * HH + 255) / 256, 256>>>();                    // 2
    router_kernel<<<BB, 256>>>(ln_gamma, ln_beta, router_w, router_b); // 3
    {
        dim3 g(HH / 32, HH / 32, EE), b(32, 8);
        convert_w_kernel<<<g, b>>>(expert_w);                          // 4
    }
    if (out_size > BB * SS * HH) {
        aux_kernel<<<1, 1>>>(out + (size_t)BB * SS * HH);              // 5
    }
    dim3 grid(HH / 256, MTOT / 128);  // (3, 512)
    gemm_tc_kernel<<<grid, 256, SMEM_TOTAL>>>(expert_b, out);          // 6
}

// round 6
// speedup vs baseline: 2.4865x; 1.2006x over previous
#include <cuda_runtime.h>
#include <cuda_bf16.h>
#include <math.h>
#include <stdint.h>

#define BB 32
#define SS 2048
#define HH 768
#define EE 2
#define MTOT (BB*SS)
#define LN_EPS 1e-5f

// GEMM: CTA 128x256, 8 warps of 64x64, BK=64, 2-stage cp.async, swizzled 128B rows
#define BK 64
#define NCHUNK (HH/BK)           // 12
#define OFF_AH 0
#define OFF_AL 16384
#define OFF_BH 32768
#define OFF_BL 65536
#define STAGE  98304
#define SMEM_TOTAL (2*STAGE)     // 196608

// -------- scratch (no allocations allowed) --------
__device__ float g_part[BB*32*HH];
__device__ float g_probs[BB*EE];
__device__ int   g_idx[BB];
__device__ __nv_bfloat16 g_ah[(size_t)MTOT*HH];
__device__ __nv_bfloat16 g_al[(size_t)MTOT*HH];
__device__ __nv_bfloat16 g_wt_hi[EE*HH*HH];   // W^T hi [e][n][k]
__device__ __nv_bfloat16 g_wt_lo[EE*HH*HH];   // W^T lo

// ---------------------------------------------------------------------------
// helpers
// ---------------------------------------------------------------------------
__device__ __forceinline__ uint32_t smem_u32(const void* p) {
    return (uint32_t)__cvta_generic_to_shared(p);
}
__device__ __forceinline__ void cp16(uint32_t dst, const void* src) {
    asm volatile("cp.async.cg.shared.global [%0], [%1], 16;" :: "r"(dst), "l"(src));
}
#define CP_COMMIT() asm volatile("cp.async.commit_group;" ::: "memory")
#define CP_WAIT0()  asm volatile("cp.async.wait_group 0;" ::: "memory")
#define CP_WAIT1()  asm volatile("cp.async.wait_group 1;" ::: "memory")

__device__ __forceinline__ void ldsm4(uint32_t* r, uint32_t addr) {
    asm volatile("ldmatrix.sync.aligned.m8n8.x4.shared.b16 {%0,%1,%2,%3}, [%4];"
                 : "=r"(r[0]), "=r"(r[1]), "=r"(r[2]), "=r"(r[3]) : "r"(addr));
}
__device__ __forceinline__ void mma16816(float* c, const uint32_t* a, const uint32_t* b) {
    asm volatile(
        "mma.sync.aligned.m16n8k16.row.col.f32.bf16.bf16.f32 "
        "{%0,%1,%2,%3}, {%4,%5,%6,%7}, {%8,%9}, {%0,%1,%2,%3};"
        : "+f"(c[0]), "+f"(c[1]), "+f"(c[2]), "+f"(c[3])
        : "r"(a[0]), "r"(a[1]), "r"(a[2]), "r"(a[3]), "r"(b[0]), "r"(b[1]));
}
__device__ __forceinline__ uint32_t pack2(__nv_bfloat16 a, __nv_bfloat16 b) {
    return (uint32_t)__bfloat16_as_ushort(a) | ((uint32_t)__bfloat16_as_ushort(b) << 16);
}

// FMA/ALU-only GELU (tanh approx == sigmoid form): no MUFU in the hot epilogue.
__device__ __forceinline__ float gelu_f(float x) {
    float u = 0.7978845608028654f * x * (1.0f + 0.044715f * x * x);
    float z = 2.885390081777927f * u;                 // 2u*log2(e)
    z = fminf(fmaxf(z, -30.0f), 30.0f);
    float nf = rintf(z);
    float f = z - nf;
    float p = 1.5403530e-4f;
    p = fmaf(p, f, 1.3333558e-3f);
    p = fmaf(p, f, 9.6181291e-3f);
    p = fmaf(p, f, 5.5504109e-2f);
    p = fmaf(p, f, 2.4022651e-1f);
    p = fmaf(p, f, 6.9314718e-1f);
    p = fmaf(p, f, 1.0f);
    float sc = __int_as_float(((int)nf + 127) << 23);
    float e = p * sc;                                 // e^{2u}
    float D = e + 1.0f;
    float r = __int_as_float(0x7EF311C3u - __float_as_int(D));
    r = r * (2.0f - D * r);
    r = r * (2.0f - D * r);
    r = r * (2.0f - D * r);                           // r = 1/(1+e^{2u})
    return x * (1.0f - r);
}

// ---------------------------------------------------------------------------
// 1: fused pool partials + A bf16 hi/lo split. grid BB*32, block 192.
// ---------------------------------------------------------------------------
__global__ void pool_split_kernel(const float* __restrict__ in) {
    int blk = blockIdx.x;
    int b = blk >> 5, c = blk & 31;
    int t = threadIdx.x;
    size_t row0 = (size_t)b * SS + (size_t)c * 64;
    float4 s = {0.f, 0.f, 0.f, 0.f};
    for (int i = 0; i < 64; i++) {
        size_t m = row0 + i;
        float4 v = *(const float4*)(in + m * HH + 4 * t);
        s.x += v.x; s.y += v.y; s.z += v.z; s.w += v.w;
        __nv_bfloat16 h0 = __float2bfloat16_rn(v.x);
        __nv_bfloat16 h1 = __float2bfloat16_rn(v.y);
        __nv_bfloat16 h2 = __float2bfloat16_rn(v.z);
        __nv_bfloat16 h3 = __float2bfloat16_rn(v.w);
        uint2 hp, lp;
        hp.x = pack2(h0, h1); hp.y = pack2(h2, h3);
        lp.x = pack2(__float2bfloat16_rn(v.x - __bfloat162float(h0)),
                     __float2bfloat16_rn(v.y - __bfloat162float(h1)));
        lp.y = pack2(__float2bfloat16_rn(v.z - __bfloat162float(h2)),
                     __float2bfloat16_rn(v.w - __bfloat162float(h3)));
        *(uint2*)(g_ah + m * HH + 4 * t) = hp;
        *(uint2*)(g_al + m * HH + 4 * t) = lp;
    }
    *(float4*)(g_part + (size_t)blk * HH + 4 * t) = s;
}

// ---------------------------------------------------------------------------
// 2: W[e][k][n] -> W^T hi/lo [e][n][k]
// ---------------------------------------------------------------------------
__global__ void convert_w_kernel(const float* __restrict__ W) {
    __shared__ float tile[32][33];
    int e = blockIdx.z;
    int k0 = blockIdx.y * 32, n0 = blockIdx.x * 32;
    int tx = threadIdx.x, ty = threadIdx.y;
    const float* Wp = W + (size_t)e * HH * HH;
    for (int i = ty; i < 32; i += 8)
        tile[i][tx] = Wp[(size_t)(k0 + i) * HH + n0 + tx];
    __syncthreads();
    __nv_bfloat16* oh = g_wt_hi + (size_t)e * HH * HH;
    __nv_bfloat16* ol = g_wt_lo + (size_t)e * HH * HH;
    for (int i = ty; i < 32; i += 8) {
        float w = tile[tx][i];
        __nv_bfloat16 hi = __float2bfloat16_rn(w);
        oh[(size_t)(n0 + i) * HH + k0 + tx] = hi;
        ol[(size_t)(n0 + i) * HH + k0 + tx] =
            __float2bfloat16_rn(w - __bfloat162float(hi));
    }
}

// ---------------------------------------------------------------------------
// 3: router with fused partial reduction. One block (256 thr) per batch.
// ---------------------------------------------------------------------------
__global__ void router_kernel(const float* __restrict__ gamma,
                              const float* __restrict__ beta,
                              const float* __restrict__ rw,
                              const float* __restrict__ rb) {
    int b = blockIdx.x;
    int t = threadIdx.x;
    __shared__ float red[256];

    float x0 = 0.f, x1 = 0.f, x2 = 0.f;
    #pragma unroll 4
    for (int c = 0; c < 32; c++) {
        const float* p = g_part + (size_t)(b * 32 + c) * HH;
        x0 += p[t]; x1 += p[t + 256]; x2 += p[t + 512];
    }
    x0 *= (1.0f / SS); x1 *= (1.0f / SS); x2 *= (1.0f / SS);

    red[t] = x0 + x1 + x2;
    __syncthreads();
    for (int o = 128; o > 0; o >>= 1) { if (t < o) red[t] += red[t + o]; __syncthreads(); }
    float mu = red[0] * (1.0f / HH);
    __syncthreads();

    float d0 = x0 - mu, d1 = x1 - mu, d2 = x2 - mu;
    red[t] = d0 * d0 + d1 * d1 + d2 * d2;
    __syncthreads();
    for (int o = 128; o > 0; o >>= 1) { if (t < o) red[t] += red[t + o]; __syncthreads(); }
    float rstd = rsqrtf(red[0] * (1.0f / HH) + LN_EPS);
    __syncthreads();

    float n0 = d0 * rstd * gamma[t]       + beta[t];
    float n1 = d1 * rstd * gamma[t + 256] + beta[t + 256];
    float n2 = d2 * rstd * gamma[t + 512] + beta[t + 512];
    float l0 = n0 * rw[t * EE]     + n1 * rw[(t + 256) * EE]     + n2 * rw[(t + 512) * EE];
    float l1 = n0 * rw[t * EE + 1] + n1 * rw[(t + 256) * EE + 1] + n2 * rw[(t + 512) * EE + 1];

    red[t] = l0;
    __syncthreads();
    for (int o = 128; o > 0; o >>= 1) { if (t < o) red[t] += red[t + o]; __syncthreads(); }
    l0 = red[0];
    __syncthreads();
    red[t] = l1;
    __syncthreads();
    for (int o = 128; o > 0; o >>= 1) { if (t < o) red[t] += red[t + o]; __syncthreads(); }

    if (t == 0) {
        l1 = red[0];
        l0 += rb[0];
        l1 += rb[1];
        float m  = fmaxf(l0, l1);
        float e0 = expf(l0 - m);
        float e1 = expf(l1 - m);
        float inv = 1.0f / (e0 + e1);
        g_probs[b * 2 + 0] = e0 * inv;
        g_probs[b * 2 + 1] = e1 * inv;
        g_idx[b] = (l1 > l0) ? 1 : 0;
    }
}

// ---------------------------------------------------------------------------
// 5: aux loss
// ---------------------------------------------------------------------------
__global__ void aux_kernel(float* __restrict__ out) {
    float a0 = 0.f, a1 = 0.f;
    for (int b = 0; b < BB; b++) { a0 += g_probs[2 * b]; a1 += g_probs[2 * b + 1]; }
    a0 *= (1.0f / BB);
    a1 *= (1.0f / BB);
    float d0 = a0 - 0.5f, d1 = a1 - 0.5f;
    out[0] = 0.01f * 0.5f * (d0 * d0 + d1 * d1);
}

// ---------------------------------------------------------------------------
// GEMM stage loader: BK=64 chunk, swizzled 128B rows, 24 cp16 per thread
// ---------------------------------------------------------------------------
__device__ __forceinline__ void load_stage(
    uint32_t st, int m0, int n0, int kt,
    const __nv_bfloat16* __restrict__ WH,
    const __nv_bfloat16* __restrict__ WL, int tid)
{
    // A: 2 halves x 128 rows x 8 chunks = 2048 cp16
    #pragma unroll
    for (int j = 0; j < 8; j++) {
        int idx = j * 256 + tid;
        int half = idx >> 10;
        int rem = idx & 1023;
        int r = rem >> 3, c = rem & 7;
        const __nv_bfloat16* base = half ? g_al : g_ah;
        cp16(st + (uint32_t)half * 16384 + (uint32_t)(r * 128 + ((c ^ (r & 7)) << 4)),
             base + (size_t)(m0 + r) * HH + kt + c * 8);
    }
    // B: 2 halves x 256 rows x 8 chunks = 4096 cp16
    #pragma unroll
    for (int j = 0; j < 16; j++) {
        int idx = j * 256 + tid;
        int half = idx >> 11;
        int rem = idx & 2047;
        int r = rem >> 3, c = rem & 7;
        const __nv_bfloat16* base = half ? WL : WH;
        cp16(st + OFF_BH + (uint32_t)half * 32768 +
                 (uint32_t)(r * 128 + ((c ^ (r & 7)) << 4)),
             base + (size_t)(n0 + r) * HH + kt + c * 8);
    }
    CP_COMMIT();
}

// ---------------------------------------------------------------------------
// 4: GEMM: C = gelu(A @ W_e + b_e), mma.sync bf16 3-term, fragment reuse
// ---------------------------------------------------------------------------
__global__ __launch_bounds__(256, 1) void gemm_tc_kernel(
    const float* __restrict__ bias,
    float* __restrict__ C)
{
    extern __shared__ char sm[];
    uint32_t sb = smem_u32(sm);
    int tid = threadIdx.x, lane = tid & 31, wid = tid >> 5;
    int mw = wid & 1;
    int nw = wid >> 1;
    int n0 = blockIdx.x * 256;
    int m0 = blockIdx.y * 128;

    int e = g_idx[m0 >> 11];
    const __nv_bfloat16* WH = g_wt_hi + (size_t)e * HH * HH;
    const __nv_bfloat16* WL = g_wt_lo + (size_t)e * HH * HH;

    float acc[4][8][4];
    #pragma unroll
    for (int mt = 0; mt < 4; mt++)
        #pragma unroll
        for (int nt = 0; nt < 8; nt++)
            #pragma unroll
            for (int q = 0; q < 4; q++) acc[mt][nt][q] = 0.f;

    // per-thread ldmatrix row bases and k-chunk selectors
    int lx = lane & 7;
    uint32_t arow = (uint32_t)((mw * 64 + (lane & 15)) * 128);
    uint32_t brow = (uint32_t)((nw * 64 + (lane & 7) + ((lane & 16) >> 1)) * 128);
    int a_ks = lane >> 4;          // 0..1
    int b_ks = (lane >> 3) & 1;    // 0..1

    load_stage(sb, m0, n0, 0, WH, WL, tid);

    for (int i = 0; i < NCHUNK; i++) {
        if (i < NCHUNK - 1) {
            load_stage(sb + (uint32_t)((i + 1) & 1) * STAGE, m0, n0, (i + 1) * BK,
                       WH, WL, tid);
            CP_WAIT1();
        } else {
            CP_WAIT0();
        }
        __syncthreads();

        uint32_t st = sb + (uint32_t)(i & 1) * STAGE;
        #pragma unroll
        for (int ks = 0; ks < 4; ks++) {
            uint32_t asel = (uint32_t)(((ks * 2 + a_ks) ^ lx) << 4);
            uint32_t bsel = (uint32_t)(((ks * 2 + b_ks) ^ lx) << 4);
            uint32_t a[4][4], al[4][4], b[4][4];
            #pragma unroll
            for (int nt2 = 0; nt2 < 4; nt2++)
                ldsm4(b[nt2], st + OFF_BH + brow + nt2 * 2048 + bsel);
            #pragma unroll
            for (int mt = 0; mt < 4; mt++)
                ldsm4(a[mt], st + OFF_AH + arow + mt * 2048 + asel);
            #pragma unroll
            for (int mt = 0; mt < 4; mt++)
                #pragma unroll
                for (int nt = 0; nt < 8; nt++)
                    mma16816(acc[mt][nt], a[mt], &b[nt >> 1][(nt & 1) * 2]);
            #pragma unroll
            for (int mt = 0; mt < 4; mt++)
                ldsm4(al[mt], st + OFF_AL + arow + mt * 2048 + asel);
            #pragma unroll
            for (int mt = 0; mt < 4; mt++)
                #pragma unroll
                for (int nt = 0; nt < 8; nt++)
                    mma16816(acc[mt][nt], al[mt], &b[nt >> 1][(nt & 1) * 2]);
            #pragma unroll
            for (int nt2 = 0; nt2 < 4; nt2++)
                ldsm4(b[nt2], st + OFF_BL + brow + nt2 * 2048 + bsel);
            #pragma unroll
            for (int mt = 0; mt < 4; mt++)
                #pragma unroll
                for (int nt = 0; nt < 8; nt++)
                    mma16816(acc[mt][nt], a[mt], &b[nt >> 1][(nt & 1) * 2]);
        }
        __syncthreads();
    }

    // epilogue: bias + gelu + store
    int ncol = n0 + nw * 64;
    const float* bp = bias + e * HH + ncol + 2 * (lane & 3);
    float2 bv[8];
    #pragma unroll
    for (int nt = 0; nt < 8; nt++) bv[nt] = *(const float2*)(bp + nt * 8);

    #pragma unroll
    for (int mt = 0; mt < 4; mt++) {
        int r0 = m0 + mw * 64 + mt * 16 + (lane >> 2);
        float* crow0 = C + (size_t)r0 * HH + ncol + 2 * (lane & 3);
        float* crow1 = crow0 + (size_t)8 * HH;
        #pragma unroll
        for (int nt = 0; nt < 8; nt++) {
            float2 o0, o1;
            o0.x = gelu_f(acc[mt][nt][0] + bv[nt].x);
            o0.y = gelu_f(acc[mt][nt][1] + bv[nt].y);
            o1.x = gelu_f(acc[mt][nt][2] + bv[nt].x);
            o1.y = gelu_f(acc[mt][nt][3] + bv[nt].y);
            *(float2*)(crow0 + nt * 8) = o0;
            *(float2*)(crow1 + nt * 8) = o1;
        }
    }
}

// ---------------------------------------------------------------------------
// Launch (GEMM is 4th launch; profiler has hit #4 both rounds)
// ---------------------------------------------------------------------------
extern "C" void kernel_launch(void* const* d_in, const int* in_sizes, int n_in,
                              void* d_out, int out_size) {
    const float* inputs   = (const float*)d_in[0];
    const float* ln_gamma = (const float*)d_in[1];
    const float* ln_beta  = (const float*)d_in[2];
    const float* router_w = (const float*)d_in[3];
    const float* router_b = (const float*)d_in[4];
    const float* expert_w = (const float*)d_in[5];
    const float* expert_b = (const float*)d_in[6];
    float* out = (float*)d_out;

    cudaFuncSetAttribute(gemm_tc_kernel,
                         cudaFuncAttributeMaxDynamicSharedMemorySize, SMEM_TOTAL);

    pool_split_kernel<<<BB * 32, 192>>>(inputs);                       // 1
    {
        dim3 g(HH / 32, HH / 32, EE), b(32, 8);
        convert_w_kernel<<<g, b>>>(expert_w);                          // 2
    }
    router_kernel<<<BB, 256>>>(ln_gamma, ln_beta, router_w, router_b); // 3
    dim3 grid(HH / 256, MTOT / 128);  // (3, 512)
    gemm_tc_kernel<<<grid, 256, SMEM_TOTAL>>>(expert_b, out);          // 4
    if (out_size > BB * SS * HH) {
        aux_kernel<<<1, 1>>>(out + (size_t)BB * SS * HH);              // 5
    }
}

// round 7
// speedup vs baseline: 2.5180x; 1.0127x over previous
#include <cuda_runtime.h>
#include <cuda_bf16.h>
#include <math.h>
#include <stdint.h>

#define BB 32
#define SS 2048
#define HH 768
#define EE 2
#define MTOT (BB*SS)
#define LN_EPS 1e-5f

// GEMM: CTA 128x256, 8 warps of 64x64, BK=64, 2-stage cp.async, swizzled 128B rows
#define BK 64
#define NCHUNK (HH/BK)           // 12
#define OFF_AH 0
#define OFF_AL 16384
#define OFF_BH 32768
#define OFF_BL 65536
#define STAGE  98304
#define SMEM_TOTAL (2*STAGE)     // 196608

// -------- scratch (no allocations allowed) --------
__device__ float g_part[BB*32*HH];
__device__ float g_probs[BB*EE];
__device__ int   g_idx[BB];
__device__ __nv_bfloat16 g_ah[(size_t)MTOT*HH];
__device__ __nv_bfloat16 g_al[(size_t)MTOT*HH];
__device__ __nv_bfloat16 g_wt_hi[EE*HH*HH];   // W^T hi [e][n][k]
__device__ __nv_bfloat16 g_wt_lo[EE*HH*HH];   // W^T lo

// ---------------------------------------------------------------------------
// helpers
// ---------------------------------------------------------------------------
__device__ __forceinline__ uint32_t smem_u32(const void* p) {
    return (uint32_t)__cvta_generic_to_shared(p);
}
__device__ __forceinline__ void cp16(uint32_t dst, const void* src) {
    asm volatile("cp.async.cg.shared.global [%0], [%1], 16;" :: "r"(dst), "l"(src));
}
#define CP_COMMIT() asm volatile("cp.async.commit_group;" ::: "memory")
#define CP_WAIT0()  asm volatile("cp.async.wait_group 0;" ::: "memory")
#define CP_WAIT1()  asm volatile("cp.async.wait_group 1;" ::: "memory")

__device__ __forceinline__ void ldsm4(uint32_t* r, uint32_t addr) {
    asm volatile("ldmatrix.sync.aligned.m8n8.x4.shared.b16 {%0,%1,%2,%3}, [%4];"
                 : "=r"(r[0]), "=r"(r[1]), "=r"(r[2]), "=r"(r[3]) : "r"(addr));
}
__device__ __forceinline__ void mma16816(float* c, const uint32_t* a, const uint32_t* b) {
    asm volatile(
        "mma.sync.aligned.m16n8k16.row.col.f32.bf16.bf16.f32 "
        "{%0,%1,%2,%3}, {%4,%5,%6,%7}, {%8,%9}, {%0,%1,%2,%3};"
        : "+f"(c[0]), "+f"(c[1]), "+f"(c[2]), "+f"(c[3])
        : "r"(a[0]), "r"(a[1]), "r"(a[2]), "r"(a[3]), "r"(b[0]), "r"(b[1]));
}
__device__ __forceinline__ uint32_t pack2(__nv_bfloat16 a, __nv_bfloat16 b) {
    return (uint32_t)__bfloat16_as_ushort(a) | ((uint32_t)__bfloat16_as_ushort(b) << 16);
}

// FMA/ALU-only GELU (tanh approx == sigmoid form): no MUFU in the hot epilogue.
__device__ __forceinline__ float gelu_f(float x) {
    float u = 0.7978845608028654f * x * (1.0f + 0.044715f * x * x);
    float z = 2.885390081777927f * u;                 // 2u*log2(e)
    z = fminf(fmaxf(z, -30.0f), 30.0f);
    float nf = rintf(z);
    float f = z - nf;
    float p = 1.5403530e-4f;
    p = fmaf(p, f, 1.3333558e-3f);
    p = fmaf(p, f, 9.6181291e-3f);
    p = fmaf(p, f, 5.5504109e-2f);
    p = fmaf(p, f, 2.4022651e-1f);
    p = fmaf(p, f, 6.9314718e-1f);
    p = fmaf(p, f, 1.0f);
    float sc = __int_as_float(((int)nf + 127) << 23);
    float e = p * sc;                                 // e^{2u}
    float D = e + 1.0f;
    float r = __int_as_float(0x7EF311C3u - __float_as_int(D));
    r = r * (2.0f - D * r);
    r = r * (2.0f - D * r);
    r = r * (2.0f - D * r);                           // r = 1/(1+e^{2u})
    return x * (1.0f - r);
}

// ---------------------------------------------------------------------------
// 1: fused pool partials + A bf16 hi/lo split. grid BB*32, block 192.
// ---------------------------------------------------------------------------
__global__ void pool_split_kernel(const float* __restrict__ in) {
    int blk = blockIdx.x;
    int b = blk >> 5, c = blk & 31;
    int t = threadIdx.x;
    size_t row0 = (size_t)b * SS + (size_t)c * 64;
    float4 s = {0.f, 0.f, 0.f, 0.f};
    for (int i = 0; i < 64; i++) {
        size_t m = row0 + i;
        float4 v = *(const float4*)(in + m * HH + 4 * t);
        s.x += v.x; s.y += v.y; s.z += v.z; s.w += v.w;
        __nv_bfloat16 h0 = __float2bfloat16_rn(v.x);
        __nv_bfloat16 h1 = __float2bfloat16_rn(v.y);
        __nv_bfloat16 h2 = __float2bfloat16_rn(v.z);
        __nv_bfloat16 h3 = __float2bfloat16_rn(v.w);
        uint2 hp, lp;
        hp.x = pack2(h0, h1); hp.y = pack2(h2, h3);
        lp.x = pack2(__float2bfloat16_rn(v.x - __bfloat162float(h0)),
                     __float2bfloat16_rn(v.y - __bfloat162float(h1)));
        lp.y = pack2(__float2bfloat16_rn(v.z - __bfloat162float(h2)),
                     __float2bfloat16_rn(v.w - __bfloat162float(h3)));
        *(uint2*)(g_ah + m * HH + 4 * t) = hp;
        *(uint2*)(g_al + m * HH + 4 * t) = lp;
    }
    *(float4*)(g_part + (size_t)blk * HH + 4 * t) = s;
}

// ---------------------------------------------------------------------------
// 2: W[e][k][n] -> W^T hi/lo [e][n][k]
// ---------------------------------------------------------------------------
__global__ void convert_w_kernel(const float* __restrict__ W) {
    __shared__ float tile[32][33];
    int e = blockIdx.z;
    int k0 = blockIdx.y * 32, n0 = blockIdx.x * 32;
    int tx = threadIdx.x, ty = threadIdx.y;
    const float* Wp = W + (size_t)e * HH * HH;
    for (int i = ty; i < 32; i += 8)
        tile[i][tx] = Wp[(size_t)(k0 + i) * HH + n0 + tx];
    __syncthreads();
    __nv_bfloat16* oh = g_wt_hi + (size_t)e * HH * HH;
    __nv_bfloat16* ol = g_wt_lo + (size_t)e * HH * HH;
    for (int i = ty; i < 32; i += 8) {
        float w = tile[tx][i];
        __nv_bfloat16 hi = __float2bfloat16_rn(w);
        oh[(size_t)(n0 + i) * HH + k0 + tx] = hi;
        ol[(size_t)(n0 + i) * HH + k0 + tx] =
            __float2bfloat16_rn(w - __bfloat162float(hi));
    }
}

// ---------------------------------------------------------------------------
// 3: router with fused partial reduction. One block (256 thr) per batch.
// ---------------------------------------------------------------------------
__global__ void router_kernel(const float* __restrict__ gamma,
                              const float* __restrict__ beta,
                              const float* __restrict__ rw,
                              const float* __restrict__ rb) {
    int b = blockIdx.x;
    int t = threadIdx.x;
    __shared__ float red[256];

    float x0 = 0.f, x1 = 0.f, x2 = 0.f;
    #pragma unroll 4
    for (int c = 0; c < 32; c++) {
        const float* p = g_part + (size_t)(b * 32 + c) * HH;
        x0 += p[t]; x1 += p[t + 256]; x2 += p[t + 512];
    }
    x0 *= (1.0f / SS); x1 *= (1.0f / SS); x2 *= (1.0f / SS);

    red[t] = x0 + x1 + x2;
    __syncthreads();
    for (int o = 128; o > 0; o >>= 1) { if (t < o) red[t] += red[t + o]; __syncthreads(); }
    float mu = red[0] * (1.0f / HH);
    __syncthreads();

    float d0 = x0 - mu, d1 = x1 - mu, d2 = x2 - mu;
    red[t] = d0 * d0 + d1 * d1 + d2 * d2;
    __syncthreads();
    for (int o = 128; o > 0; o >>= 1) { if (t < o) red[t] += red[t + o]; __syncthreads(); }
    float rstd = rsqrtf(red[0] * (1.0f / HH) + LN_EPS);
    __syncthreads();

    float n0 = d0 * rstd * gamma[t]       + beta[t];
    float n1 = d1 * rstd * gamma[t + 256] + beta[t + 256];
    float n2 = d2 * rstd * gamma[t + 512] + beta[t + 512];
    float l0 = n0 * rw[t * EE]     + n1 * rw[(t + 256) * EE]     + n2 * rw[(t + 512) * EE];
    float l1 = n0 * rw[t * EE + 1] + n1 * rw[(t + 256) * EE + 1] + n2 * rw[(t + 512) * EE + 1];

    red[t] = l0;
    __syncthreads();
    for (int o = 128; o > 0; o >>= 1) { if (t < o) red[t] += red[t + o]; __syncthreads(); }
    l0 = red[0];
    __syncthreads();
    red[t] = l1;
    __syncthreads();
    for (int o = 128; o > 0; o >>= 1) { if (t < o) red[t] += red[t + o]; __syncthreads(); }

    if (t == 0) {
        l1 = red[0];
        l0 += rb[0];
        l1 += rb[1];
        float m  = fmaxf(l0, l1);
        float e0 = expf(l0 - m);
        float e1 = expf(l1 - m);
        float inv = 1.0f / (e0 + e1);
        g_probs[b * 2 + 0] = e0 * inv;
        g_probs[b * 2 + 1] = e1 * inv;
        g_idx[b] = (l1 > l0) ? 1 : 0;
    }
}

// ---------------------------------------------------------------------------
// 5: aux loss
// ---------------------------------------------------------------------------
__global__ void aux_kernel(float* __restrict__ out) {
    float a0 = 0.f, a1 = 0.f;
    for (int b = 0; b < BB; b++) { a0 += g_probs[2 * b]; a1 += g_probs[2 * b + 1]; }
    a0 *= (1.0f / BB);
    a1 *= (1.0f / BB);
    float d0 = a0 - 0.5f, d1 = a1 - 0.5f;
    out[0] = 0.01f * 0.5f * (d0 * d0 + d1 * d1);
}

// ---------------------------------------------------------------------------
// GEMM stage loader: BK=64 chunk, swizzled 128B rows, 24 cp16 per thread
// ---------------------------------------------------------------------------
__device__ __forceinline__ void load_stage(
    uint32_t st, int m0, int n0, int kt,
    const __nv_bfloat16* __restrict__ WH,
    const __nv_bfloat16* __restrict__ WL, int tid)
{
    // A: 2 halves x 128 rows x 8 chunks = 2048 cp16
    #pragma unroll
    for (int j = 0; j < 8; j++) {
        int idx = j * 256 + tid;
        int half = idx >> 10;
        int rem = idx & 1023;
        int r = rem >> 3, c = rem & 7;
        const __nv_bfloat16* base = half ? g_al : g_ah;
        cp16(st + (uint32_t)half * 16384 + (uint32_t)(r * 128 + ((c ^ (r & 7)) << 4)),
             base + (size_t)(m0 + r) * HH + kt + c * 8);
    }
    // B: 2 halves x 256 rows x 8 chunks = 4096 cp16
    #pragma unroll
    for (int j = 0; j < 16; j++) {
        int idx = j * 256 + tid;
        int half = idx >> 11;
        int rem = idx & 2047;
        int r = rem >> 3, c = rem & 7;
        const __nv_bfloat16* base = half ? WL : WH;
        cp16(st + OFF_BH + (uint32_t)half * 32768 +
                 (uint32_t)(r * 128 + ((c ^ (r & 7)) << 4)),
             base + (size_t)(n0 + r) * HH + kt + c * 8);
    }
    CP_COMMIT();
}

// ---------------------------------------------------------------------------
// 4: GEMM: C = gelu(A @ W_e + b_e).  3-term bf16 split, product chain
//    hl -> hh -> lh so only TWO fragment arrays are live (reg pressure fix).
// ---------------------------------------------------------------------------
__global__ __launch_bounds__(256, 1) void gemm_tc_kernel(
    const float* __restrict__ bias,
    float* __restrict__ C)
{
    extern __shared__ char sm[];
    uint32_t sb = smem_u32(sm);
    int tid = threadIdx.x, lane = tid & 31, wid = tid >> 5;
    int mw = wid & 1;
    int nw = wid >> 1;
    int n0 = blockIdx.x * 256;
    int m0 = blockIdx.y * 128;

    int e = g_idx[m0 >> 11];
    const __nv_bfloat16* WH = g_wt_hi + (size_t)e * HH * HH;
    const __nv_bfloat16* WL = g_wt_lo + (size_t)e * HH * HH;

    float acc[4][8][4];
    #pragma unroll
    for (int mt = 0; mt < 4; mt++)
        #pragma unroll
        for (int nt = 0; nt < 8; nt++)
            #pragma unroll
            for (int q = 0; q < 4; q++) acc[mt][nt][q] = 0.f;

    // per-thread ldmatrix row bases and k-chunk selectors
    int lx = lane & 7;
    uint32_t arow = (uint32_t)((mw * 64 + (lane & 15)) * 128);
    uint32_t brow = (uint32_t)((nw * 64 + (lane & 7) + ((lane & 16) >> 1)) * 128);
    int a_ks = lane >> 4;          // 0..1
    int b_ks = (lane >> 3) & 1;    // 0..1

    load_stage(sb, m0, n0, 0, WH, WL, tid);

    for (int i = 0; i < NCHUNK; i++) {
        if (i < NCHUNK - 1) {
            load_stage(sb + (uint32_t)((i + 1) & 1) * STAGE, m0, n0, (i + 1) * BK,
                       WH, WL, tid);
            CP_WAIT1();
        } else {
            CP_WAIT0();
        }
        __syncthreads();

        uint32_t st = sb + (uint32_t)(i & 1) * STAGE;
        #pragma unroll
        for (int ks = 0; ks < 4; ks++) {
            uint32_t asel = (uint32_t)(((ks * 2 + a_ks) ^ lx) << 4);
            uint32_t bsel = (uint32_t)(((ks * 2 + b_ks) ^ lx) << 4);
            uint32_t a[4][4], b[4][4];
            // ---- product 1: Ah x Bl ----
            #pragma unroll
            for (int mt = 0; mt < 4; mt++)
                ldsm4(a[mt], st + OFF_AH + arow + mt * 2048 + asel);
            #pragma unroll
            for (int nt2 = 0; nt2 < 4; nt2++)
                ldsm4(b[nt2], st + OFF_BL + brow + nt2 * 2048 + bsel);
            #pragma unroll
            for (int mt = 0; mt < 4; mt++)
                #pragma unroll
                for (int nt = 0; nt < 8; nt++)
                    mma16816(acc[mt][nt], a[mt], &b[nt >> 1][(nt & 1) * 2]);
            // ---- product 2: Ah x Bh (reload b only) ----
            #pragma unroll
            for (int nt2 = 0; nt2 < 4; nt2++)
                ldsm4(b[nt2], st + OFF_BH + brow + nt2 * 2048 + bsel);
            #pragma unroll
            for (int mt = 0; mt < 4; mt++)
                #pragma unroll
                for (int nt = 0; nt < 8; nt++)
                    mma16816(acc[mt][nt], a[mt], &b[nt >> 1][(nt & 1) * 2]);
            // ---- product 3: Al x Bh (reload a only) ----
            #pragma unroll
            for (int mt = 0; mt < 4; mt++)
                ldsm4(a[mt], st + OFF_AL + arow + mt * 2048 + asel);
            #pragma unroll
            for (int mt = 0; mt < 4; mt++)
                #pragma unroll
                for (int nt = 0; nt < 8; nt++)
                    mma16816(acc[mt][nt], a[mt], &b[nt >> 1][(nt & 1) * 2]);
        }
        __syncthreads();
    }

    // epilogue: bias + gelu + store
    int ncol = n0 + nw * 64;
    const float* bp = bias + e * HH + ncol + 2 * (lane & 3);
    float2 bv[8];
    #pragma unroll
    for (int nt = 0; nt < 8; nt++) bv[nt] = *(const float2*)(bp + nt * 8);

    #pragma unroll
    for (int mt = 0; mt < 4; mt++) {
        int r0 = m0 + mw * 64 + mt * 16 + (lane >> 2);
        float* crow0 = C + (size_t)r0 * HH + ncol + 2 * (lane & 3);
        float* crow1 = crow0 + (size_t)8 * HH;
        #pragma unroll
        for (int nt = 0; nt < 8; nt++) {
            float2 o0, o1;
            o0.x = gelu_f(acc[mt][nt][0] + bv[nt].x);
            o0.y = gelu_f(acc[mt][nt][1] + bv[nt].y);
            o1.x = gelu_f(acc[mt][nt][2] + bv[nt].x);
            o1.y = gelu_f(acc[mt][nt][3] + bv[nt].y);
            *(float2*)(crow0 + nt * 8) = o0;
            *(float2*)(crow1 + nt * 8) = o1;
        }
    }
}

// ---------------------------------------------------------------------------
// Launch (GEMM is the profiled 4th launch)
// ---------------------------------------------------------------------------
extern "C" void kernel_launch(void* const* d_in, const int* in_sizes, int n_in,
                              void* d_out, int out_size) {
    const float* inputs   = (const float*)d_in[0];
    const float* ln_gamma = (const float*)d_in[1];
    const float* ln_beta  = (const float*)d_in[2];
    const float* router_w = (const float*)d_in[3];
    const float* router_b = (const float*)d_in[4];
    const float* expert_w = (const float*)d_in[5];
    const float* expert_b = (const float*)d_in[6];
    float* out = (float*)d_out;

    cudaFuncSetAttribute(gemm_tc_kernel,
                         cudaFuncAttributeMaxDynamicSharedMemorySize, SMEM_TOTAL);

    pool_split_kernel<<<BB * 32, 192>>>(inputs);                       // 1
    {
        dim3 g(HH / 32, HH / 32, EE), b(32, 8);
        convert_w_kernel<<<g, b>>>(expert_w);                          // 2
    }
    router_kernel<<<BB, 256>>>(ln_gamma, ln_beta, router_w, router_b); // 3
    dim3 grid(HH / 256, MTOT / 128);  // (3, 512)
    gemm_tc_kernel<<<grid, 256, SMEM_TOTAL>>>(expert_b, out);          // 4
    if (out_size > BB * SS * HH) {
        aux_kernel<<<1, 1>>>(out + (size_t)BB * SS * HH);              // 5
    }
}